// round 6
// baseline (speedup 1.0000x reference)
#include <cuda_runtime.h>
#include <math_constants.h>

#define BATCH 262144
#define NLAYER 8
#define H 128
#define NSEG 129
#define BN_EPS 1e-5f
#define FLOW_EPS 1e-4f
#define INVALID 0xFFFFFFFFu
#define NREP 4

// ---------------- device scratch (no allocs allowed) ----------------
__device__ double g_sum[2];                        // sum(u), sum(u^2) of next-layer input
__device__ int    g_cntR[NREP][NSEG];              // replicated per-segment counts
__device__ float  g_s1R[NREP][NSEG], g_s2R[NREP][NSEG];
__device__ float  g_theta[H];                      // sorted kinks
__device__ __align__(16) float g_tab[NSEG * H * 2];
__device__ __align__(16) float2 g_ghbh[H];         // BN2 fold factors per j
__device__ int    g_off[NSEG + 1], g_cursor[NSEG], g_ptotal;
__device__ int    g_flag;                          // "offsets ready" flag
__device__ unsigned g_perm[BATCH + NSEG * 32];
__device__ unsigned char g_mseg[BATCH];
__device__ float g_x[2 * BATCH];
__device__ float g_sldj[BATCH];

// ---------------- init: copy x, zero sldj, stats of x1 ----------------
__global__ void k_init(const float* __restrict__ x)
{
    int tid = blockIdx.x * blockDim.x + threadIdx.x;
    int stride = gridDim.x * blockDim.x;
    float kS = 0.f, cS = 0.f, kQ = 0.f, cQ = 0.f;
    for (int i = tid; i < BATCH; i += stride) {
        float2 p = ((const float2*)x)[i];
        ((float2*)g_x)[i] = p;
        g_sldj[i] = 0.f;
        float v = p.y;
        { float yk = v - cS; float tk = kS + yk; cS = (tk - kS) - yk; kS = tk; }
        float v2 = v * v;
        { float yk = v2 - cQ; float tk = kQ + yk; cQ = (tk - kQ) - yk; kQ = tk; }
    }
    double s = (double)kS, q = (double)kQ;
    for (int off = 16; off; off >>= 1) {
        s += __shfl_down_sync(0xffffffffu, s, off);
        q += __shfl_down_sync(0xffffffffu, q, off);
    }
    __shared__ double ss[32], sq[32];
    int lane = threadIdx.x & 31, w = threadIdx.x >> 5;
    if (!lane) { ss[w] = s; sq[w] = q; }
    __syncthreads();
    if (!w) {
        int nw = blockDim.x >> 5;
        s = (lane < nw) ? ss[lane] : 0.0;
        q = (lane < nw) ? sq[lane] : 0.0;
        for (int off = 16; off; off >>= 1) {
            s += __shfl_down_sync(0xffffffffu, s, off);
            q += __shfl_down_sync(0xffffffffu, q, off);
        }
        if (!lane) { atomicAdd(&g_sum[0], s); atomicAdd(&g_sum[1], q); }
    }
}

// ---------------- prep: fold BN1, sort kinks, build segment A/B table ----------------
__global__ void k_prep(int l,
    const float* __restrict__ v1, const float* __restrict__ g1, const float* __restrict__ b1,
    const float* __restrict__ bn1g, const float* __restrict__ bn1b,
    const float* __restrict__ v2, const float* __restrict__ g2, const float* __restrict__ b2)
{
    extern __shared__ float smp[];
    float* sa   = smp;
    float* sc   = sa + H;
    float* sthr = sc + H;
    int*   sord = (int*)(sthr + H);
    float* sv2  = (float*)(sord + H);   // [j][k] padded stride 129

    int t = threadIdx.x;   // 0..255
    if (t < H) {
        int k = t;
        double mu  = g_sum[0] * (1.0 / BATCH);
        double var = g_sum[1] * (1.0 / BATCH) - mu * mu;
        float meanu = (float)mu;
        float varu  = (float)(var < 0.0 ? 0.0 : var);
        float v  = v1[l * H + k];
        float w1 = g1[l * H + k] * (v / fabsf(v));
        float r  = rsqrtf(w1 * w1 * varu + BN_EPS);
        float a  = w1 * bn1g[l * H + k] * r;
        float c  = bn1b[l * H + k] - a * meanu;
        sa[k] = a; sc[k] = c;
        sthr[k] = (a != 0.f) ? (-c / a) : CUDART_INF_F;
    }
    __syncthreads();
    if (t < H) {
        int k = t;
        float th = sthr[k];
        int rank = 0;
        for (int j = 0; j < H; j++) {
            float tj = sthr[j];
            rank += (tj < th) || (tj == th && j < k);
        }
        sord[rank] = k;
        g_theta[rank] = th;
    }
    // overlap: all 256 threads stream v2 into padded smem while ranks compute
    for (int idx = t; idx < H * H; idx += 256) {
        int row = idx >> 7, col = idx & 127;
        sv2[row * 129 + col] = v2[l * H * H + idx];
    }
    __syncthreads();

    if (t < H) {
        int j = t;
        float nrm = 0.f;
        for (int tt = 0; tt < H; tt++) { float x = sv2[j * 129 + tt]; nrm = fmaf(x, x, nrm); }
        float wsc = g2[l * H + j] / sqrtf(nrm);

        float A = 0.f, Bv = b2[l * H + j];
        for (int tt = 0; tt < H; tt++) {
            float aa = sa[tt], cc = sc[tt];
            float w = wsc * sv2[j * 129 + tt];
            if (aa < 0.f)                     { A += w * aa; Bv += w * cc; }
            else if (aa == 0.f && cc > 0.f)   { Bv += w * cc; }
        }
        g_tab[(0 * H + j) * 2]     = A;
        g_tab[(0 * H + j) * 2 + 1] = Bv;

        for (int m = 1; m <= H; m++) {
            int kk = sord[m - 1];
            float aa = sa[kk], cc = sc[kk];
            float w = wsc * sv2[j * 129 + kk];
            float sgn = (aa > 0.f) ? 1.f : ((aa < 0.f) ? -1.f : 0.f);
            A  += sgn * w * aa;
            Bv += sgn * w * cc;
            g_tab[(m * H + j) * 2]     = A;
            g_tab[(m * H + j) * 2 + 1] = Bv;
        }
    }
}

// ---------------- hist: fp32/int smem atomics; warp-reduced hot tails ----------------
#define HIST_B 148
#define HIST_T 1024
__global__ void __launch_bounds__(HIST_T) k_hist(int uIdx)
{
    __shared__ float sth[H];
    __shared__ int   scnt[NSEG];
    __shared__ float ss1[NSEG], ss2[NSEG];
    int t = threadIdx.x;
    if (t < H) sth[t] = g_theta[t];
    for (int i = t; i < NSEG; i += HIST_T) { scnt[i] = 0; ss1[i] = 0.f; ss2[i] = 0.f; }
    __syncthreads();

    int lane = t & 31;
    int tid = blockIdx.x * HIST_T + t;
    int stride = gridDim.x * HIST_T;
    // BATCH and stride are multiples of 32 -> warp-uniform trip count (ballots safe)
    for (int i = tid; i < BATCH; i += stride) {
        float2 p = ((const float2*)g_x)[i];
        float u = uIdx ? p.y : p.x;
        int m = 0;
#pragma unroll
        for (int s = 64; s >= 1; s >>= 1) { int nm = m + s; if (sth[nm - 1] < u) m = nm; }
        if (sth[H - 1] < u) m = H;   // 7-step count saturates at 127
        g_mseg[i] = (unsigned char)m;

        bool lo = (m == 0), hi = (m == H);
        float u2 = u * u;
        float s1l = lo ? u : 0.f, s2l = lo ? u2 : 0.f;
        float s1h = hi ? u : 0.f, s2h = hi ? u2 : 0.f;
#pragma unroll
        for (int off = 16; off; off >>= 1) {
            s1l += __shfl_xor_sync(0xffffffffu, s1l, off);
            s2l += __shfl_xor_sync(0xffffffffu, s2l, off);
            s1h += __shfl_xor_sync(0xffffffffu, s1h, off);
            s2h += __shfl_xor_sync(0xffffffffu, s2h, off);
        }
        unsigned blo = __ballot_sync(0xffffffffu, lo);
        unsigned bhi = __ballot_sync(0xffffffffu, hi);
        if (lane == 0) {
            if (blo) { atomicAdd(&scnt[0], __popc(blo)); atomicAdd(&ss1[0], s1l); atomicAdd(&ss2[0], s2l); }
            if (bhi) { atomicAdd(&scnt[H], __popc(bhi)); atomicAdd(&ss1[H], s1h); atomicAdd(&ss2[H], s2h); }
        }
        if (!lo && !hi) {
            atomicAdd(&scnt[m], 1);
            atomicAdd(&ss1[m], u);
            atomicAdd(&ss2[m], u2);
        }
    }
    __syncthreads();
    int r = blockIdx.x & (NREP - 1);
    for (int i = t; i < NSEG; i += HIST_T) {
        if (scnt[i]) {
            atomicAdd(&g_cntR[r][i], scnt[i]);
            atomicAdd(&g_s1R[r][i], ss1[i]);
            atomicAdd(&g_s2R[r][i], ss2[i]);
        }
    }
}

// ---------------- scatfold: block 0 = offsets (flag) + BN2 fold; blocks 1.. = scatter ----------------
#define SCAT_T 256
#define SCAT_B 512
__global__ void __launch_bounds__(SCAT_T) k_scatfold(int l,
    const float* __restrict__ bn2g, const float* __restrict__ bn2b)
{
    int t = threadIdx.x;
    if (blockIdx.x == 0) {
        __shared__ int ecnt[NSEG], eoff[NSEG + 1];
        __shared__ float sN[NSEG], s1v[NSEG], s2v[NSEG];
        __shared__ float red1[SCAT_T], red2[SCAT_T];

        // --- critical path for workers: counts -> offsets -> cursors/padding -> flag ---
        for (int m = t; m < NSEG; m += SCAT_T) {
            int c = 0;
#pragma unroll
            for (int r = 0; r < NREP; r++) c += g_cntR[r][m];
            ecnt[m] = c;
            sN[m] = (float)c;
        }
        __syncthreads();
        if (t == 0) {
            int run = 0;
            for (int s = 0; s < NSEG; s++) { eoff[s] = run; run += (ecnt[s] + 31) & ~31; }
            eoff[NSEG] = run;
            g_ptotal = run;
            g_off[NSEG] = run;
            g_sum[0] = 0.0; g_sum[1] = 0.0;
        }
        __syncthreads();
        for (int m = t; m < NSEG; m += SCAT_T) {
            g_off[m] = eoff[m];
            g_cursor[m] = 0;
            for (int p = eoff[m] + ecnt[m]; p < eoff[m + 1]; p++) g_perm[p] = INVALID;
        }
        __threadfence();
        __syncthreads();
        if (t == 0) atomicExch(&g_flag, 1);

        // --- BN2 fold (fp32 Kahan), off workers' critical path ---
        for (int m = t; m < NSEG; m += SCAT_T) {
            float a = 0.f, b = 0.f;
#pragma unroll
            for (int r = 0; r < NREP; r++) { a += g_s1R[r][m]; b += g_s2R[r][m]; }
            s1v[m] = a; s2v[m] = b;
        }
        __syncthreads();
        int j = t & 127, half = t >> 7;
        float a1 = 0.f, c1 = 0.f, a2 = 0.f, c2 = 0.f;
        for (int m = half; m < NSEG; m += 2) {
            float2 ab = ((const float2*)g_tab)[m * H + j];
            float N = sN[m], S1 = s1v[m], S2 = s2v[m];
            float t1 = ab.x * S1 + ab.y * N;
            float t2 = ab.x * ab.x * S2 + 2.f * ab.x * ab.y * S1 + ab.y * ab.y * N;
            { float yk = t1 - c1; float tk = a1 + yk; c1 = (tk - a1) - yk; a1 = tk; }
            { float yk = t2 - c2; float tk = a2 + yk; c2 = (tk - a2) - yk; a2 = tk; }
        }
        red1[t] = a1; red2[t] = a2;
        __syncthreads();
        if (half == 0) {
            float m1 = red1[t] + red1[t + 128];
            float m2 = red2[t] + red2[t + 128];
            float mean = m1 * (1.f / BATCH);
            float var  = m2 * (1.f / BATCH) - mean * mean;
            if (var < 0.f) var = 0.f;
            float gh = bn2g[l * H + j] * rsqrtf(var + BN_EPS);
            float bh = bn2b[l * H + j] - gh * mean;
            g_ghbh[j] = make_float2(gh, bh);
        }
    } else {
        __shared__ int bcnt[NSEG], bbase[NSEG], soff[NSEG];
        for (int i = t; i < NSEG; i += SCAT_T) bcnt[i] = 0;
        __syncthreads();
        // local histogram ranks BEFORE waiting on the flag (overlaps block0's work)
        int base = (blockIdx.x - 1) * SCAT_T * 2;
        int i0 = base + t, i1 = base + SCAT_T + t;
        int m0 = g_mseg[i0], m1 = g_mseg[i1];
        int r0 = atomicAdd(&bcnt[m0], 1);
        int r1 = atomicAdd(&bcnt[m1], 1);
        __syncthreads();
        if (t == 0) { while (atomicAdd(&g_flag, 0) == 0) __nanosleep(64); }
        __syncthreads();
        __threadfence();
        for (int i = t; i < NSEG; i += SCAT_T) {
            soff[i] = g_off[i];
            bbase[i] = bcnt[i] ? atomicAdd(&g_cursor[i], bcnt[i]) : 0;
        }
        __syncthreads();
        g_perm[soff[m0] + bbase[m0] + r0] = ((unsigned)m0 << 18) | (unsigned)i0;
        g_perm[soff[m1] + bbase[m1] + r1] = ((unsigned)m1 << 18) | (unsigned)i1;
    }
}

// ---------------- apply: warp-uniform segment, one sample per lane ----------------
__global__ void __launch_bounds__(1024, 1) k_apply(
    int uIdx, int isLast, int l,
    const float* __restrict__ wf, const float* __restrict__ bf,
    float* __restrict__ out)
{
    extern __shared__ float4 stab4[];          // NSEG*64 folded rows + 64 wf float4
    float4* wf4 = stab4 + NSEG * 64;
    const float4* ghbh4 = (const float4*)g_ghbh;   // (gh0,bh0,gh1,bh1) per j-pair
    for (int idx = threadIdx.x; idx < NSEG * 64; idx += blockDim.x) {
        float4 tv = ((const float4*)g_tab)[idx];
        float4 gb = __ldg(&ghbh4[idx & 63]);
        stab4[idx] = make_float4(gb.x * tv.x, fmaf(gb.x, tv.y, gb.y),
                                 gb.z * tv.z, fmaf(gb.z, tv.w, gb.w));
    }
    for (int jj = threadIdx.x; jj < 64; jj += blockDim.x) {
        int j0 = 2 * jj, j1 = 2 * jj + 1;
        wf4[jj] = make_float4(wf[(l * 2 + 0) * H + j0], wf[(l * 2 + 1) * H + j0],
                              wf[(l * 2 + 0) * H + j1], wf[(l * 2 + 1) * H + j1]);
    }
    // block 0: reset flag + zero replicated seg-stat scratch for the NEXT hist
    if (blockIdx.x == 0) {
        if (threadIdx.x == 0) g_flag = 0;
        for (int idx = threadIdx.x; idx < NREP * NSEG; idx += blockDim.x) {
            ((int*)g_cntR)[idx] = 0;
            ((float*)g_s1R)[idx] = 0.f;
            ((float*)g_s2R)[idx] = 0.f;
        }
    }
    __syncthreads();

    int lane = threadIdx.x & 31, wid = threadIdx.x >> 5;
    float bf0 = bf[l * 2], bf1 = bf[l * 2 + 1];
    int oIdx = 1 - uIdx;
    int P = g_ptotal;

    float kS = 0.f, cS = 0.f, kQ = 0.f, cQ = 0.f;   // Kahan fp32 accumulators
    int gw = blockIdx.x * (blockDim.x >> 5) + wid;
    int nw = gridDim.x * (blockDim.x >> 5);

    for (int base = gw * 32; base < P; base += nw * 32) {
        unsigned pv  = g_perm[base + lane];
        unsigned pv0 = __shfl_sync(0xffffffffu, pv, 0);   // lane 0 valid (32-aligned regions)
        int m0 = (int)(pv0 >> 18);
        bool valid = (pv != INVALID);
        unsigned i = valid ? (pv & 0x3FFFFu) : 0u;

        float2 p = ((const float2*)g_x)[i];
        float u  = uIdx ? p.y : p.x;
        float xo = uIdx ? p.x : p.y;

        const float4* row = stab4 + m0 * 64;
        float st0a = 0.f, st1a = 0.f, st0b = 0.f, st1b = 0.f;
#pragma unroll 8
        for (int c = 0; c < 64; c += 2) {
            float4 tv = row[c];     float4 w4 = wf4[c];
            float h0 = fmaxf(fmaf(tv.x, u, tv.y), 0.f);
            float h1 = fmaxf(fmaf(tv.z, u, tv.w), 0.f);
            st0a = fmaf(w4.x, h0, fmaf(w4.z, h1, st0a));
            st1a = fmaf(w4.y, h0, fmaf(w4.w, h1, st1a));
            float4 tv2 = row[c + 1]; float4 w42 = wf4[c + 1];
            float h2 = fmaxf(fmaf(tv2.x, u, tv2.y), 0.f);
            float h3 = fmaxf(fmaf(tv2.z, u, tv2.w), 0.f);
            st0b = fmaf(w42.x, h2, fmaf(w42.z, h3, st0b));
            st1b = fmaf(w42.y, h2, fmaf(w42.w, h3, st1b));
        }
        float st0 = st0a + st0b + bf0;
        float st1 = st1a + st1b + bf1;
        float e2  = __expf(2.f * st0);
        float sv  = 1.f - 2.f * __fdividef(1.f, e2 + 1.f);   // tanh(st0)
        float y   = fmaf(__expf(sv), xo, st1);

        if (valid) {
            float sld = g_sldj[i] + sv;
            if (!isLast) {
                g_x[2 * i + oIdx] = y;
                g_sldj[i] = sld;
                { float yk = y - cS;  float tk = kS + yk; cS = (tk - kS) - yk; kS = tk; }
                float yy = y * y;
                { float yk = yy - cQ; float tk = kQ + yk; cQ = (tk - kQ) - yk; kQ = tk; }
            } else {
                float zu = __fdividef(1.f, 1.f + __expf(-u));
                float zo = __fdividef(1.f, 1.f + __expf(-y));
                sld += __logf(zu * (1.f - zu) + FLOW_EPS) + __logf(zo * (1.f - zo) + FLOW_EPS);
                out[2 * i + uIdx] = zu;
                out[2 * i + oIdx] = zo;
                out[2 * BATCH + i] = sld;
            }
        }
    }

    if (!isLast) {
        double s = (double)kS, q = (double)kQ;
        for (int off = 16; off; off >>= 1) {
            s += __shfl_down_sync(0xffffffffu, s, off);
            q += __shfl_down_sync(0xffffffffu, q, off);
        }
        __shared__ double rs[32], rq[32];
        if (!lane) { rs[wid] = s; rq[wid] = q; }
        __syncthreads();
        if (!wid) {
            int nwb = blockDim.x >> 5;
            s = (lane < nwb) ? rs[lane] : 0.0;
            q = (lane < nwb) ? rq[lane] : 0.0;
            for (int off = 16; off; off >>= 1) {
                s += __shfl_down_sync(0xffffffffu, s, off);
                q += __shfl_down_sync(0xffffffffu, q, off);
            }
            if (!lane) { atomicAdd(&g_sum[0], s); atomicAdd(&g_sum[1], q); }
        }
    }
}

// ---------------- host launcher ----------------
extern "C" void kernel_launch(void* const* d_in, const int* in_sizes, int n_in,
                              void* d_out, int out_size)
{
    const float* x    = (const float*)d_in[0];
    const float* v1   = (const float*)d_in[1];
    const float* g1   = (const float*)d_in[2];
    const float* b1   = (const float*)d_in[3];
    const float* bn1g = (const float*)d_in[4];
    const float* bn1b = (const float*)d_in[5];
    const float* v2   = (const float*)d_in[6];
    const float* g2   = (const float*)d_in[7];
    const float* b2   = (const float*)d_in[8];
    const float* bn2g = (const float*)d_in[9];
    const float* bn2b = (const float*)d_in[10];
    const float* wf   = (const float*)d_in[11];
    const float* bf   = (const float*)d_in[12];
    float* out = (float*)d_out;

    const int SMEM_PREP  = (3 * H) * 4 + H * 4 + H * 129 * 4;                 // ~68 KB
    const int SMEM_APPLY = (NSEG * 64 + 64) * (int)sizeof(float4);            // 133120 B
    cudaFuncSetAttribute(k_prep,  cudaFuncAttributeMaxDynamicSharedMemorySize, SMEM_PREP);
    cudaFuncSetAttribute(k_apply, cudaFuncAttributeMaxDynamicSharedMemorySize, SMEM_APPLY);

    k_init<<<512, 256>>>(x);
    for (int l = 0; l < NLAYER; l++) {
        int uIdx = (l % 2 == 0) ? 1 : 0;
        int isLast = (l == NLAYER - 1) ? 1 : 0;
        k_prep<<<1, 256, SMEM_PREP>>>(l, v1, g1, b1, bn1g, bn1b, v2, g2, b2);
        k_hist<<<HIST_B, HIST_T>>>(uIdx);
        k_scatfold<<<SCAT_B + 1, SCAT_T>>>(l, bn2g, bn2b);
        k_apply<<<148, 1024, SMEM_APPLY>>>(uIdx, isLast, l, wf, bf, out);
    }
    (void)in_sizes; (void)n_in; (void)out_size;
}

// round 7
// speedup vs baseline: 1.2783x; 1.2783x over previous
#include <cuda_runtime.h>
#include <math_constants.h>

#define BATCH 262144
#define NLAYER 8
#define H 128
#define NSEG 129
#define BN_EPS 1e-5f
#define FLOW_EPS 1e-4f
#define INVALID 0xFFFFFFFFu
#define NREP 4
#define NB 148
#define NT 1024

// ---------------- device scratch (no allocs allowed) ----------------
__device__ unsigned g_arrive = 0, g_release = 0;   // grid barrier (monotonic, replay-safe)
__device__ double g_sum[2][2];                     // [parity][s,q]
__device__ int    g_cntR[2][NREP][NSEG];
__device__ float  g_s1R[2][NREP][NSEG], g_s2R[2][NREP][NSEG];
__device__ __align__(16) float g_tab[NSEG * H * 2];
__device__ int    g_cursor[2][NSEG];
__device__ unsigned g_perm[BATCH + NSEG * 32];
__device__ unsigned char g_mseg[BATCH];
__device__ float g_x[2 * BATCH];
__device__ float g_sldj[BATCH];

// grid-wide barrier: all NB blocks resident by construction
__device__ __forceinline__ void gridbar()
{
    __syncthreads();
    if (threadIdx.x == 0) {
        unsigned old = *(volatile unsigned*)&g_release;
        __threadfence();
        if (atomicAdd(&g_arrive, 1) == NB - 1) {
            atomicExch(&g_arrive, 0);
            __threadfence();
            atomicExch(&g_release, old + 1);
        } else {
            while (*(volatile unsigned*)&g_release == old) __nanosleep(64);
        }
        __threadfence();
    }
    __syncthreads();
}

// shared layout (floats) within the extra region after the 133120-byte table area
#define XO_SA    0
#define XO_SC    128
#define XO_STHR  256
#define XO_STHS  384
#define XO_SORD  512
#define XO_SVR   640
#define XO_SCANA 768
#define XO_SCANB 900
#define XO_SCNT  1032
#define XO_SS1   1164
#define XO_SS2   1296
#define XO_EOFF  1428
#define XO_SNI   1560
#define XO_S1V   1692
#define XO_S2V   1824
#define XO_GHBH  1956
#define XO_RED1  2212
#define XO_RED2  3236
#define XO_MISC  4260
#define X_FLOATS 4352
#define SMEM_ALL (NSEG * 64 * 16 + 64 * 16 + X_FLOATS * 4)

__global__ void __launch_bounds__(NT, 1) k_all(
    const float* __restrict__ x,
    const float* __restrict__ v1,  const float* __restrict__ g1,  const float* __restrict__ b1,
    const float* __restrict__ bn1g,const float* __restrict__ bn1b,
    const float* __restrict__ v2,  const float* __restrict__ g2,  const float* __restrict__ b2,
    const float* __restrict__ bn2g,const float* __restrict__ bn2b,
    const float* __restrict__ wf,  const float* __restrict__ bf,
    float* __restrict__ out)
{
    extern __shared__ float sm[];
    float4* stab4 = (float4*)sm;                 // NSEG*64 float4 table
    float4* wf4   = stab4 + NSEG * 64;           // 64 float4
    float*  X     = (float*)(wf4 + 64);

    const int t = threadIdx.x, b = blockIdx.x;
    const int lane = t & 31, wid = t >> 5;

    // ================= P0: copy x, stats of x[:,1] into g_sum[0] =================
    {
        float kS = 0.f, cS = 0.f, kQ = 0.f, cQ = 0.f;
        for (int i = b * NT + t; i < BATCH; i += NB * NT) {
            float2 p = ((const float2*)x)[i];
            __stcg(((float2*)g_x) + i, p);
            float v = p.y;
            { float yk = v - cS; float tk = kS + yk; cS = (tk - kS) - yk; kS = tk; }
            float v2s = v * v;
            { float yk = v2s - cQ; float tk = kQ + yk; cQ = (tk - kQ) - yk; kQ = tk; }
        }
        double s = (double)kS, q = (double)kQ;
        for (int off = 16; off; off >>= 1) {
            s += __shfl_down_sync(0xffffffffu, s, off);
            q += __shfl_down_sync(0xffffffffu, q, off);
        }
        __shared__ double ss[32], sq[32];
        if (!lane) { ss[wid] = s; sq[wid] = q; }
        __syncthreads();
        if (!wid) {
            s = (lane < NT / 32) ? ss[lane] : 0.0;
            q = (lane < NT / 32) ? sq[lane] : 0.0;
            for (int off = 16; off; off >>= 1) {
                s += __shfl_down_sync(0xffffffffu, s, off);
                q += __shfl_down_sync(0xffffffffu, q, off);
            }
            if (!lane) { atomicAdd(&g_sum[0][0], s); atomicAdd(&g_sum[0][1], q); }
        }
        // re-zero parity-0 buffers (idempotent; also statically zero on first run)
        if (b == 1) {
            for (int idx = t; idx < NREP * NSEG; idx += NT) {
                ((int*)g_cntR[0])[idx] = 0;
                ((float*)g_s1R[0])[idx] = 0.f;
                ((float*)g_s2R[0])[idx] = 0.f;
            }
            for (int idx = t; idx < NSEG; idx += NT) g_cursor[0][idx] = 0;
        }
    }
    gridbar();

    for (int l = 0; l < NLAYER; l++) {
        const int par = l & 1, nxt = par ^ 1;
        const int uIdx = (l & 1) ^ 1, oIdx = 1 - uIdx;
        const int isLast = (l == NLAYER - 1);

        // ================= P12: BN1 fold + sort (in-block), tab build, hist =================
        float* sa = X + XO_SA; float* sc = X + XO_SC; float* sthr = X + XO_STHR;
        float* sths = X + XO_STHS; int* sord = (int*)(X + XO_SORD); float* svr = X + XO_SVR;
        float* scanA = X + XO_SCANA; float* scanB = X + XO_SCANB;
        int* scnt = (int*)(X + XO_SCNT); float* ss1 = X + XO_SS1; float* ss2 = X + XO_SS2;
        float* redA = X + XO_RED1; float* redB = X + XO_RED2;
        float* miscf = X + XO_MISC;

        if (t < H) {
            double mu = __ldcg(&g_sum[par][0]) * (1.0 / BATCH);
            double qq = __ldcg(&g_sum[par][1]) * (1.0 / BATCH);
            double var = qq - mu * mu;
            float meanu = (float)mu;
            float varu = (float)(var < 0.0 ? 0.0 : var);
            float v  = v1[l * H + t];
            float w1 = g1[l * H + t] * (v / fabsf(v));
            float r  = rsqrtf(w1 * w1 * varu + BN_EPS);
            float a  = w1 * bn1g[l * H + t] * r;
            float c  = bn1b[l * H + t] - a * meanu;
            sa[t] = a; sc[t] = c;
            sthr[t] = (a != 0.f) ? (-c / a) : CUDART_INF_F;
        }
        __syncthreads();
        if (t < H) {
            float th = sthr[t];
            int rank = 0;
            for (int j2 = 0; j2 < H; j2++) {
                float tj = sthr[j2];
                rank += (tj < th) || (tj == th && j2 < t);
            }
            sths[rank] = th; sord[rank] = t;
        }
        // block NB-1: zero next-parity buffers (global)
        if (b == NB - 1) {
            for (int idx = t; idx < NREP * NSEG; idx += NT) {
                ((int*)g_cntR[nxt])[idx] = 0;
                ((float*)g_s1R[nxt])[idx] = 0.f;
                ((float*)g_s2R[nxt])[idx] = 0.f;
            }
            for (int idx = t; idx < NSEG; idx += NT) g_cursor[nxt][idx] = 0;
        }
        __syncthreads();

        // blocks 0..127: build table column j=b with parallel prefix scan
        if (b < H) {
            const int j = b;
            if (t < H) svr[t] = v2[l * H * H + j * H + t];
            __syncthreads();
            if (t == 0) {
                float nrm = 0.f;
                for (int tt = 0; tt < H; tt++) nrm = fmaf(svr[tt], svr[tt], nrm);
                miscf[0] = g2[l * H + j] / sqrtf(nrm);
            }
            __syncthreads();
            float wsc = miscf[0];
            if (t < H) {
                float aa = sa[t], cc = sc[t], w = wsc * svr[t];
                redA[t] = (aa < 0.f) ? w * aa : 0.f;
                redB[t] = (aa < 0.f) ? w * cc : ((aa == 0.f && cc > 0.f) ? w * cc : 0.f);
            }
            if (t >= 1 && t <= H) {
                int kk = sord[t - 1];
                float aa = sa[kk], cc = sc[kk], w = wsc * svr[kk];
                float sgn = (aa > 0.f) ? 1.f : ((aa < 0.f) ? -1.f : 0.f);
                scanA[t] = sgn * w * aa;
                scanB[t] = sgn * w * cc;
            }
            if (t == 0) { scanA[0] = 0.f; scanB[0] = 0.f; }
            __syncthreads();
            if (t == 0) {
                float A0 = 0.f, B0 = b2[l * H + j];
                for (int tt = 0; tt < H; tt++) { A0 += redA[tt]; B0 += redB[tt]; }
                miscf[1] = A0; miscf[2] = B0;
            }
            // Hillis-Steele inclusive scan over indices 1..128
            for (int off = 1; off <= H; off <<= 1) {
                float aadd = 0.f, badd = 0.f;
                if (t >= off && t <= H) { aadd = scanA[t - off]; badd = scanB[t - off]; }
                __syncthreads();
                if (t >= off && t <= H) { scanA[t] += aadd; scanB[t] += badd; }
                __syncthreads();
            }
            if (t <= H) {
                float2 val = make_float2(miscf[1] + scanA[t], miscf[2] + scanB[t]);
                __stcg(((float2*)g_tab) + t * H + j, val);
            }
        }
        __syncthreads();

        // hist
        for (int i = t; i < NSEG; i += NT) { scnt[i] = 0; ss1[i] = 0.f; ss2[i] = 0.f; }
        __syncthreads();
        for (int i = b * NT + t; i < BATCH; i += NB * NT) {
            float2 p = __ldcg(((const float2*)g_x) + i);
            float u = uIdx ? p.y : p.x;
            int m = 0;
#pragma unroll
            for (int s = 64; s >= 1; s >>= 1) { int nm = m + s; if (sths[nm - 1] < u) m = nm; }
            if (sths[H - 1] < u) m = H;   // 7-step count saturates at 127
            __stcg(&g_mseg[i], (unsigned char)m);

            bool lo = (m == 0), hi = (m == H);
            float u2 = u * u;
            float s1l = lo ? u : 0.f, s2l = lo ? u2 : 0.f;
            float s1h = hi ? u : 0.f, s2h = hi ? u2 : 0.f;
#pragma unroll
            for (int off = 16; off; off >>= 1) {
                s1l += __shfl_xor_sync(0xffffffffu, s1l, off);
                s2l += __shfl_xor_sync(0xffffffffu, s2l, off);
                s1h += __shfl_xor_sync(0xffffffffu, s1h, off);
                s2h += __shfl_xor_sync(0xffffffffu, s2h, off);
            }
            unsigned blo = __ballot_sync(0xffffffffu, lo);
            unsigned bhi = __ballot_sync(0xffffffffu, hi);
            if (lane == 0) {
                if (blo) { atomicAdd(&scnt[0], (int)__popc(blo)); atomicAdd(&ss1[0], s1l); atomicAdd(&ss2[0], s2l); }
                if (bhi) { atomicAdd(&scnt[H], (int)__popc(bhi)); atomicAdd(&ss1[H], s1h); atomicAdd(&ss2[H], s2h); }
            }
            if (!lo && !hi) {
                atomicAdd(&scnt[m], 1);
                atomicAdd(&ss1[m], u);
                atomicAdd(&ss2[m], u2);
            }
        }
        __syncthreads();
        {
            int r = b & (NREP - 1);
            for (int i = t; i < NSEG; i += NT) {
                if (scnt[i]) {
                    atomicAdd(&g_cntR[par][r][i], scnt[i]);
                    atomicAdd(&g_s1R[par][r][i], ss1[i]);
                    atomicAdd(&g_s2R[par][r][i], ss2[i]);
                }
            }
        }
        gridbar();

        // ================= P3: local offsets, padding, scatter =================
        {
            int* ecnt = scnt;
            int* eoff = (int*)(X + XO_EOFF);
            int* bcnt = (int*)(X + XO_SS1);
            int* bbase = (int*)(X + XO_SS2);
            if (t < NSEG) {
                int c = 0;
#pragma unroll
                for (int r = 0; r < NREP; r++) c += __ldcg(&g_cntR[par][r][t]);
                ecnt[t] = c;
            }
            for (int i = t; i < NSEG; i += NT) bcnt[i] = 0;
            __syncthreads();
            if (t == 0) {
                int run = 0;
                for (int s = 0; s < NSEG; s++) { eoff[s] = run; run += (ecnt[s] + 31) & ~31; }
                eoff[NSEG] = run;
                if (b == 0) { g_sum[nxt][0] = 0.0; g_sum[nxt][1] = 0.0; }
            }
            __syncthreads();
            if (b < NSEG) {
                for (int p = eoff[b] + ecnt[b] + t; p < eoff[b + 1]; p += NT)
                    __stcg(&g_perm[p], INVALID);
            }
            if (b < 128) {
                int i0 = b * 2048 + t, i1 = i0 + 1024;
                int m0 = __ldcg(&g_mseg[i0]);
                int m1 = __ldcg(&g_mseg[i1]);
                int r0 = atomicAdd(&bcnt[m0], 1);
                int r1 = atomicAdd(&bcnt[m1], 1);
                __syncthreads();
                if (t < NSEG) bbase[t] = bcnt[t] ? atomicAdd(&g_cursor[par][t], bcnt[t]) : 0;
                __syncthreads();
                __stcg(&g_perm[eoff[m0] + bbase[m0] + r0], ((unsigned)m0 << 18) | (unsigned)i0);
                __stcg(&g_perm[eoff[m1] + bbase[m1] + r1], ((unsigned)m1 << 18) | (unsigned)i1);
            }
        }
        gridbar();

        // ================= P4: in-block BN2 fold + apply =================
        {
            int* sNi = (int*)(X + XO_SNI);
            float* s1v = X + XO_S1V; float* s2v = X + XO_S2V;
            float* ghbhS = X + XO_GHBH;
            float* red1 = X + XO_RED1; float* red2 = X + XO_RED2;
            int* misc = (int*)(X + XO_MISC);

            for (int idx = t; idx < NSEG * 64; idx += NT)
                stab4[idx] = __ldcg(((const float4*)g_tab) + idx);
            if (t < NSEG) {
                int c = 0; float a = 0.f, bb = 0.f;
#pragma unroll
                for (int r = 0; r < NREP; r++) {
                    c  += __ldcg(&g_cntR[par][r][t]);
                    a  += __ldcg(&g_s1R[par][r][t]);
                    bb += __ldcg(&g_s2R[par][r][t]);
                }
                sNi[t] = c; s1v[t] = a; s2v[t] = bb;
            }
            for (int jj = t; jj < 64; jj += NT) {
                int j0 = 2 * jj, j1 = 2 * jj + 1;
                wf4[jj] = make_float4(wf[(l * 2 + 0) * H + j0], wf[(l * 2 + 1) * H + j0],
                                      wf[(l * 2 + 0) * H + j1], wf[(l * 2 + 1) * H + j1]);
            }
            __syncthreads();
            {
                int j = t & 127, c = t >> 7;
                float a1 = 0.f, a2 = 0.f;
                for (int m = c; m < NSEG; m += 8) {
                    float4 q4 = stab4[m * 64 + (j >> 1)];
                    float A  = (j & 1) ? q4.z : q4.x;
                    float Bv = (j & 1) ? q4.w : q4.y;
                    float N = (float)sNi[m], S1 = s1v[m], S2 = s2v[m];
                    a1 += A * S1 + Bv * N;
                    a2 += A * (A * S2 + 2.f * Bv * S1) + Bv * Bv * N;
                }
                red1[t] = a1; red2[t] = a2;
            }
            __syncthreads();
            if (t < H) {
                float m1 = 0.f, m2 = 0.f;
#pragma unroll
                for (int c = 0; c < 8; c++) { m1 += red1[c * 128 + t]; m2 += red2[c * 128 + t]; }
                float mean = m1 * (1.f / BATCH);
                float var  = m2 * (1.f / BATCH) - mean * mean;
                if (var < 0.f) var = 0.f;
                float gh = bn2g[l * H + t] * rsqrtf(var + BN_EPS);
                float bh = bn2b[l * H + t] - gh * mean;
                ghbhS[2 * t] = gh; ghbhS[2 * t + 1] = bh;
            }
            if (t == 0) {
                int run = 0;
                for (int s = 0; s < NSEG; s++) run += (sNi[s] + 31) & ~31;
                misc[0] = run;
            }
            __syncthreads();
            for (int idx = t; idx < NSEG * 64; idx += NT) {
                float4 v4 = stab4[idx];
                int jp = (idx & 63) * 2;
                float g0 = ghbhS[2 * jp], b0 = ghbhS[2 * jp + 1];
                float g1v = ghbhS[2 * jp + 2], b1v = ghbhS[2 * jp + 3];
                stab4[idx] = make_float4(g0 * v4.x, fmaf(g0, v4.y, b0),
                                         g1v * v4.z, fmaf(g1v, v4.w, b1v));
            }
            __syncthreads();

            const int P = misc[0];
            float bf0 = bf[l * 2], bf1 = bf[l * 2 + 1];
            float kS = 0.f, cS = 0.f, kQ = 0.f, cQ = 0.f;
            int gw = b * 32 + wid, nw = NB * 32;

            for (int base = gw * 32; base < P; base += nw * 32) {
                unsigned pv  = __ldcg(&g_perm[base + lane]);
                unsigned pv0 = __shfl_sync(0xffffffffu, pv, 0);
                int m0 = (int)(pv0 >> 18);
                bool valid = (pv != INVALID);
                unsigned i = valid ? (pv & 0x3FFFFu) : 0u;

                float2 p = __ldcg(((const float2*)g_x) + i);
                float u  = uIdx ? p.y : p.x;
                float xo = uIdx ? p.x : p.y;

                const float4* row = stab4 + m0 * 64;
                float st0a = 0.f, st1a = 0.f, st0b = 0.f, st1b = 0.f;
#pragma unroll 8
                for (int c = 0; c < 64; c += 2) {
                    float4 tv = row[c];     float4 w4 = wf4[c];
                    float h0 = fmaxf(fmaf(tv.x, u, tv.y), 0.f);
                    float h1 = fmaxf(fmaf(tv.z, u, tv.w), 0.f);
                    st0a = fmaf(w4.x, h0, fmaf(w4.z, h1, st0a));
                    st1a = fmaf(w4.y, h0, fmaf(w4.w, h1, st1a));
                    float4 tv2 = row[c + 1]; float4 w42 = wf4[c + 1];
                    float h2 = fmaxf(fmaf(tv2.x, u, tv2.y), 0.f);
                    float h3 = fmaxf(fmaf(tv2.z, u, tv2.w), 0.f);
                    st0b = fmaf(w42.x, h2, fmaf(w42.z, h3, st0b));
                    st1b = fmaf(w42.y, h2, fmaf(w42.w, h3, st1b));
                }
                float st0 = st0a + st0b + bf0;
                float st1 = st1a + st1b + bf1;
                float e2  = __expf(2.f * st0);
                float sv  = 1.f - 2.f * __fdividef(1.f, e2 + 1.f);
                float y   = fmaf(__expf(sv), xo, st1);

                if (valid) {
                    float sld = (l == 0 ? 0.f : __ldcg(&g_sldj[i])) + sv;
                    if (!isLast) {
                        __stcg(&g_x[2 * i + oIdx], y);
                        __stcg(&g_sldj[i], sld);
                        { float yk = y - cS;  float tk = kS + yk; cS = (tk - kS) - yk; kS = tk; }
                        float yy = y * y;
                        { float yk = yy - cQ; float tk = kQ + yk; cQ = (tk - kQ) - yk; kQ = tk; }
                    } else {
                        float zu = __fdividef(1.f, 1.f + __expf(-u));
                        float zo = __fdividef(1.f, 1.f + __expf(-y));
                        sld += __logf(zu * (1.f - zu) + FLOW_EPS) + __logf(zo * (1.f - zo) + FLOW_EPS);
                        out[2 * i + uIdx] = zu;
                        out[2 * i + oIdx] = zo;
                        out[2 * BATCH + i] = sld;
                    }
                }
            }

            if (!isLast) {
                double s = (double)kS, q = (double)kQ;
                for (int off = 16; off; off >>= 1) {
                    s += __shfl_down_sync(0xffffffffu, s, off);
                    q += __shfl_down_sync(0xffffffffu, q, off);
                }
                __shared__ double rs[32], rq[32];
                if (!lane) { rs[wid] = s; rq[wid] = q; }
                __syncthreads();
                if (!wid) {
                    s = (lane < NT / 32) ? rs[lane] : 0.0;
                    q = (lane < NT / 32) ? rq[lane] : 0.0;
                    for (int off = 16; off; off >>= 1) {
                        s += __shfl_down_sync(0xffffffffu, s, off);
                        q += __shfl_down_sync(0xffffffffu, q, off);
                    }
                    if (!lane) { atomicAdd(&g_sum[nxt][0], s); atomicAdd(&g_sum[nxt][1], q); }
                }
            } else {
                if (b == 0 && t == 0) {
                    g_sum[0][0] = 0.0; g_sum[0][1] = 0.0;
                    g_sum[1][0] = 0.0; g_sum[1][1] = 0.0;
                }
            }
        }
        if (!isLast) gridbar();
    }
}

// ---------------- host launcher ----------------
extern "C" void kernel_launch(void* const* d_in, const int* in_sizes, int n_in,
                              void* d_out, int out_size)
{
    const float* x    = (const float*)d_in[0];
    const float* v1   = (const float*)d_in[1];
    const float* g1   = (const float*)d_in[2];
    const float* b1   = (const float*)d_in[3];
    const float* bn1g = (const float*)d_in[4];
    const float* bn1b = (const float*)d_in[5];
    const float* v2   = (const float*)d_in[6];
    const float* g2   = (const float*)d_in[7];
    const float* b2   = (const float*)d_in[8];
    const float* bn2g = (const float*)d_in[9];
    const float* bn2b = (const float*)d_in[10];
    const float* wf   = (const float*)d_in[11];
    const float* bf   = (const float*)d_in[12];
    float* out = (float*)d_out;

    cudaFuncSetAttribute(k_all, cudaFuncAttributeMaxDynamicSharedMemorySize, SMEM_ALL);
    k_all<<<NB, NT, SMEM_ALL>>>(x, v1, g1, b1, bn1g, bn1b, v2, g2, b2,
                                bn2g, bn2b, wf, bf, out);
    (void)in_sizes; (void)n_in; (void)out_size;
}